// round 14
// baseline (speedup 1.0000x reference)
#include <cuda_runtime.h>
#include <cuda_bf16.h>
#include <math.h>

// ---------------------------------------------------------------------------
// SwinV2 window attention, sm_103a (compute_103 PTX).
// GEMMs via mma.sync bf16 hi/lo (3-MMA), 48KB-smem tiles for occupancy.
// Pipeline: prep_weights + convert_x + cpb -> qkv_mma -> attn -> proj_mma
// ---------------------------------------------------------------------------

#define NTOK   262144           // 16*128*128 tokens
#define NWIN   4096
#define HEADS  4
#define DIM    128
#define QKVC   384
#define LOG100 4.605170185988091f

__device__ float g_qkv[(size_t)NWIN * 64 * QKVC];   // [win][n][384] q|k|v
__device__ float g_bias[HEADS * 64 * 64];
// activations pre-split to bf16 hi/lo
__device__ __nv_bfloat16 g_xh[(size_t)NTOK * 128], g_xl[(size_t)NTOK * 128];
__device__ __nv_bfloat16 g_ah[(size_t)NTOK * 128], g_al[(size_t)NTOK * 128];
// weights pre-transposed to [n][k], split into bf16 hi/lo
__device__ __nv_bfloat16 g_wq_hi[QKVC * 128], g_wq_lo[QKVC * 128];
__device__ __nv_bfloat16 g_wp_hi[DIM  * 128], g_wp_lo[DIM  * 128];

typedef unsigned long long u64;
typedef unsigned int u32;

__device__ __forceinline__ u64 pack2(float lo, float hi) {
    u64 r; asm("mov.b64 %0, {%1,%2};" : "=l"(r) : "f"(lo), "f"(hi)); return r;
}
__device__ __forceinline__ void unpack2(u64 v, float& lo, float& hi) {
    asm("mov.b64 {%0,%1}, %2;" : "=f"(lo), "=f"(hi) : "l"(v));
}
__device__ __forceinline__ u64 ffma2(u64 a, u64 b, u64 c) {
    u64 d; asm("fma.rn.f32x2 %0, %1, %2, %3;" : "=l"(d) : "l"(a), "l"(b), "l"(c));
    return d;
}
__device__ __forceinline__ u64 fadd2(u64 a, u64 b) {
    u64 d; asm("add.rn.f32x2 %0, %1, %2;" : "=l"(d) : "l"(a), "l"(b));
    return d;
}
__device__ __forceinline__ u32 smem_u32(const void* p) {
    u32 a; asm("{ .reg .u64 t; cvta.to.shared.u64 t, %1; cvt.u32.u64 %0, t; }"
               : "=r"(a) : "l"(p));
    return a;
}
__device__ __forceinline__ void ldsm4(u32* r, u32 addr) {
    asm volatile("ldmatrix.sync.aligned.m8n8.x4.shared.b16 {%0,%1,%2,%3}, [%4];"
                 : "=r"(r[0]), "=r"(r[1]), "=r"(r[2]), "=r"(r[3]) : "r"(addr));
}
__device__ __forceinline__ void mma16816(float* c, const u32* a, const u32* b) {
    asm volatile(
        "mma.sync.aligned.m16n8k16.row.col.f32.bf16.bf16.f32 "
        "{%0,%1,%2,%3}, {%4,%5,%6,%7}, {%8,%9}, {%0,%1,%2,%3};"
        : "+f"(c[0]), "+f"(c[1]), "+f"(c[2]), "+f"(c[3])
        : "r"(a[0]), "r"(a[1]), "r"(a[2]), "r"(a[3]), "r"(b[0]), "r"(b[1]));
}

__device__ __forceinline__ void cvt_hilo4(float4 v, uint2& h, uint2& l) {
    float f[4] = {v.x, v.y, v.z, v.w};
    u32 hs[4], ls[4];
#pragma unroll
    for (int j = 0; j < 4; ++j) {
        __nv_bfloat16 hb = __float2bfloat16(f[j]);
        float hf = __bfloat162float(hb);
        __nv_bfloat16 lb = __float2bfloat16(f[j] - hf);
        hs[j] = __bfloat16_as_ushort(hb);
        ls[j] = __bfloat16_as_ushort(lb);
    }
    h.x = hs[0] | (hs[1] << 16); h.y = hs[2] | (hs[3] << 16);
    l.x = ls[0] | (ls[1] << 16); l.y = ls[2] | (ls[3] << 16);
}

// ---------------------------------------------------------------------------
// GEMM tiles: 128M x 64N, K chunks of 64. smem 48KB (4 bf16 tiles).
// Tile rows are 64 bf16 = 128B; XOR swizzle on 16B chunks.
// ---------------------------------------------------------------------------
#define AH_OFF 0
#define AL_OFF 16384
#define BH_OFF 32768
#define BL_OFF 40960
#define SMEM_G 49152

__device__ __forceinline__ u32 swz64(int r, int c8) {
    return (u32)(r * 128 + ((c8 ^ (r & 7)) << 4));
}

__device__ __forceinline__ void gemm_chunk_load(
    const __nv_bfloat16* __restrict__ Ah, const __nv_bfloat16* __restrict__ Al,
    const __nv_bfloat16* __restrict__ Bh, const __nv_bfloat16* __restrict__ Bl,
    char* smem, int tid, int rm0, int n0, int kc)
{
#pragma unroll
    for (int l = 0; l < 4; ++l) {           // A: 128 rows x 64 k
        int i = tid + l * 256;
        int r = i >> 3, c8 = i & 7;
        u32 so = swz64(r, c8);
        size_t gs = (size_t)(rm0 + r) * 128 + kc * 64 + c8 * 8;
        *(uint4*)(smem + AH_OFF + so) = *(const uint4*)&Ah[gs];
        *(uint4*)(smem + AL_OFF + so) = *(const uint4*)&Al[gs];
    }
#pragma unroll
    for (int l = 0; l < 2; ++l) {           // B: 64 rows x 64 k
        int i = tid + l * 256;
        int r = i >> 3, c8 = i & 7;
        u32 so = swz64(r, c8);
        size_t gs = (size_t)(n0 + r) * 128 + kc * 64 + c8 * 8;
        *(uint4*)(smem + BH_OFF + so) = *(const uint4*)&Bh[gs];
        *(uint4*)(smem + BL_OFF + so) = *(const uint4*)&Bl[gs];
    }
}

// warp tile 32Mx32N: acc[2 mt][4 nt][4]
__device__ __forceinline__ void gemm_chunk_mma(u32 sb, int lane, int wm, int wn,
                                               float acc[2][4][4])
{
    int ar = (lane & 7) + ((lane >> 3) & 1) * 8;
    int ac = (lane >> 4) * 8;
    int br = (lane & 7) + (lane >> 4) * 8;
    int bc = ((lane >> 3) & 1) * 8;
#pragma unroll
    for (int k0 = 0; k0 < 64; k0 += 16) {
        u32 aH[2][4], aL[2][4];
#pragma unroll
        for (int mt = 0; mt < 2; ++mt) {
            int R = wm * 32 + mt * 16 + ar;
            u32 o = swz64(R, (k0 + ac) >> 3);
            ldsm4(aH[mt], sb + AH_OFF + o);
            ldsm4(aL[mt], sb + AL_OFF + o);
        }
        u32 bH[4][2], bL[4][2];
#pragma unroll
        for (int p = 0; p < 2; ++p) {
            int R = wn * 32 + p * 16 + br;
            u32 o = swz64(R, (k0 + bc) >> 3);
            u32 t4[4];
            ldsm4(t4, sb + BH_OFF + o);
            bH[p*2][0] = t4[0]; bH[p*2][1] = t4[1];
            bH[p*2+1][0] = t4[2]; bH[p*2+1][1] = t4[3];
            ldsm4(t4, sb + BL_OFF + o);
            bL[p*2][0] = t4[0]; bL[p*2][1] = t4[1];
            bL[p*2+1][0] = t4[2]; bL[p*2+1][1] = t4[3];
        }
#pragma unroll
        for (int mt = 0; mt < 2; ++mt)
#pragma unroll
            for (int nt = 0; nt < 4; ++nt) {
                mma16816(acc[mt][nt], aH[mt], bH[nt]);
                mma16816(acc[mt][nt], aH[mt], bL[nt]);
                mma16816(acc[mt][nt], aL[mt], bH[nt]);
            }
    }
}

// ---------------------------------------------------------------------------
// prep kernels
// ---------------------------------------------------------------------------
__global__ void prep_weights_kernel(const float* __restrict__ qkv_w,
                                    const float* __restrict__ proj_w)
{
    int tid = blockIdx.x * blockDim.x + threadIdx.x;
    for (int i = tid; i < QKVC * 128 + DIM * 128; i += gridDim.x * blockDim.x) {
        float w;
        __nv_bfloat16 *dh, *dl;
        int idx;
        if (i < QKVC * 128) {
            int n = i >> 7, k = i & 127;
            w = qkv_w[k * QKVC + n];
            dh = g_wq_hi; dl = g_wq_lo; idx = i;
        } else {
            int j = i - QKVC * 128;
            int n = j >> 7, k = j & 127;
            w = proj_w[k * DIM + n];
            dh = g_wp_hi; dl = g_wp_lo; idx = j;
        }
        __nv_bfloat16 hb = __float2bfloat16(w);
        __nv_bfloat16 lb = __float2bfloat16(w - __bfloat162float(hb));
        dh[idx] = hb; dl[idx] = lb;
    }
}

__global__ void convert_x_kernel(const float* __restrict__ X)
{
    int i = blockIdx.x * blockDim.x + threadIdx.x;
    const int total = NTOK * 128 / 4;
    for (; i < total; i += gridDim.x * blockDim.x) {
        float4 v = ((const float4*)X)[i];
        uint2 h, l; cvt_hilo4(v, h, l);
        *(uint2*)&g_xh[(size_t)i * 4] = h;
        *(uint2*)&g_xl[(size_t)i * 4] = l;
    }
}

__global__ void cpb_bias_kernel(const float* __restrict__ w1,
                                const float* __restrict__ b1,
                                const float* __restrict__ w2)
{
    __shared__ float tab[225 * 4];
    int t = threadIdx.x;
    if (t < 225) {
        int i = t / 15, j = t % 15;
        float v0 = (float)(i - 7) * (8.0f / 7.0f);
        float v1 = (float)(j - 7) * (8.0f / 7.0f);
        float t0 = copysignf(log2f(fabsf(v0) + 1.0f) * (1.0f / 3.0f), v0);
        float t1 = copysignf(log2f(fabsf(v1) + 1.0f) * (1.0f / 3.0f), v1);
        float a0 = 0.f, a1 = 0.f, a2 = 0.f, a3 = 0.f;
        for (int jj = 0; jj < 512; ++jj) {
            float hsum = fmaxf(t0 * w1[jj] + t1 * w1[512 + jj] + b1[jj], 0.0f);
            a0 += hsum * w2[jj * 4 + 0];
            a1 += hsum * w2[jj * 4 + 1];
            a2 += hsum * w2[jj * 4 + 2];
            a3 += hsum * w2[jj * 4 + 3];
        }
        tab[t * 4 + 0] = a0; tab[t * 4 + 1] = a1;
        tab[t * 4 + 2] = a2; tab[t * 4 + 3] = a3;
    }
    __syncthreads();
    for (int p = t; p < HEADS * 64 * 64; p += blockDim.x) {
        int h = p >> 12, q = (p >> 6) & 63, k = p & 63;
        int r0 = (q >> 3) - (k >> 3);
        int r1 = (q & 7) - (k & 7);
        int idx = (r0 + 7) * 15 + (r1 + 7);
        float bt = tab[idx * 4 + h];
        g_bias[p] = 16.0f / (1.0f + expf(-bt));
    }
}

// ---------------------------------------------------------------------------
// Kernel 1: QKV GEMM (grid 2048 x 6), fused bias + window-partition scatter
// ---------------------------------------------------------------------------
__global__ void __launch_bounds__(256, 3) qkv_mma_kernel(
    const float* __restrict__ qb, const float* __restrict__ vb)
{
    __shared__ __align__(16) char smem[SMEM_G];
    u32 sb = smem_u32(smem);
    int tid = threadIdx.x;
    int rm0 = blockIdx.x * 128;
    int n0  = blockIdx.y * 64;

    float acc[2][4][4];
#pragma unroll
    for (int mt = 0; mt < 2; ++mt)
#pragma unroll
        for (int nt = 0; nt < 4; ++nt)
#pragma unroll
            for (int e = 0; e < 4; ++e) acc[mt][nt][e] = 0.0f;

    int lane = tid & 31, wid = tid >> 5;
    int wm = wid & 3, wn = wid >> 2;

#pragma unroll
    for (int kc = 0; kc < 2; ++kc) {
        if (kc) __syncthreads();
        gemm_chunk_load(g_xh, g_xl, g_wq_hi, g_wq_lo, smem, tid, rm0, n0, kc);
        __syncthreads();
        gemm_chunk_mma(sb, lane, wm, wn, acc);
    }

    int g = lane >> 2, t2 = (lane & 3) * 2;
    int colb = n0 + wn * 32 + t2;

    float bias0[4], bias1[4];
#pragma unroll
    for (int nt = 0; nt < 4; ++nt) {
        int c = colb + nt * 8;
        bias0[nt] = (c < 128) ? qb[c] : ((c < 256) ? 0.0f : vb[c - 256]);
        c += 1;
        bias1[nt] = (c < 128) ? qb[c] : ((c < 256) ? 0.0f : vb[c - 256]);
    }

#pragma unroll
    for (int mt = 0; mt < 2; ++mt) {
#pragma unroll
        for (int half = 0; half < 2; ++half) {
            int gr = rm0 + wm * 32 + mt * 16 + g + half * 8;
            int b   = gr >> 14;
            int rem = gr & 16383;
            int y = rem >> 7, xx = rem & 127;
            int wi = ((y >> 3) << 4) + (xx >> 3);
            int n  = ((y & 7) << 3) + (xx & 7);
            float* dst = &g_qkv[(size_t)(((b << 8) + wi) * 64 + n) * QKVC];
#pragma unroll
            for (int nt = 0; nt < 4; ++nt) {
                float2 v = make_float2(acc[mt][nt][half * 2 + 0] + bias0[nt],
                                       acc[mt][nt][half * 2 + 1] + bias1[nt]);
                *(float2*)&dst[colb + nt * 8] = v;
            }
        }
    }
}

// ---------------------------------------------------------------------------
// Kernel 2: per-(window, head) cosine attention, v3 (float4 smem, 4-way ILP)
// ---------------------------------------------------------------------------
__global__ void __launch_bounds__(64) attn_kernel(
    const float* __restrict__ mask, const float* __restrict__ logit_scale)
{
    __shared__ __align__(16) float ks[64 * 36];
    __shared__ __align__(16) float vs[64 * 36];
    __shared__ float rk[64];
    __shared__ __align__(16) float bm[64 * 68];

    int t = threadIdx.x;
    int win = blockIdx.x;
    int h   = blockIdx.y;
    int wi  = win & 255;

    const float* base = &g_qkv[(size_t)win * 64 * QKVC];

    // K,V tiles (padded stride 36 floats), float4-coalesced
#pragma unroll
    for (int i = 0; i < 8; ++i) {
        int idx4 = t + i * 64;
        int n = idx4 >> 3, d4 = (idx4 & 7) << 2;
        *(float4*)&vs[n * 36 + d4] = *(const float4*)&base[n * QKVC + 256 + h * 32 + d4];
        *(float4*)&ks[n * 36 + d4] = *(const float4*)&base[n * QKVC + 128 + h * 32 + d4];
    }
    // bias + mask (padded stride 68)
    {
        const float* gb = &g_bias[h * 4096];
        const float* gm = &mask[(size_t)wi * 4096];
#pragma unroll
        for (int i = 0; i < 16; ++i) {
            int idx4 = t + i * 64;
            int q = idx4 >> 4, k4 = (idx4 & 15) << 2;
            float4 a = *(const float4*)&gb[q * 64 + k4];
            float4 b = *(const float4*)&gm[q * 64 + k4];
            *(float4*)&bm[q * 68 + k4] =
                make_float4(a.x + b.x, a.y + b.y, a.z + b.z, a.w + b.w);
        }
    }
    // own query row into regs
    float4 q4[8];
    const float* qp = &base[t * QKVC + h * 32];
    float ssqq = 0.0f;
#pragma unroll
    for (int i = 0; i < 8; ++i) {
        q4[i] = *(const float4*)(qp + 4 * i);
        ssqq += q4[i].x * q4[i].x + q4[i].y * q4[i].y
              + q4[i].z * q4[i].z + q4[i].w * q4[i].w;
    }
    float rq = 1.0f / fmaxf(sqrtf(ssqq), 1e-12f);
    float s  = expf(fminf(logit_scale[h], LOG100));
    float rqs = rq * s;
    u64 q2[16];
#pragma unroll
    for (int i = 0; i < 8; ++i) {
        q2[2 * i]     = pack2(q4[i].x, q4[i].y);
        q2[2 * i + 1] = pack2(q4[i].z, q4[i].w);
    }
    __syncthreads();

    // per-row K inverse norms (thread t handles row t)
    {
        float ssq = 0.0f;
#pragma unroll
        for (int j = 0; j < 8; ++j) {
            float4 kv = *(const float4*)&ks[t * 36 + j * 4];
            ssq += kv.x * kv.x + kv.y * kv.y + kv.z * kv.z + kv.w * kv.w;
        }
        rk[t] = 1.0f / fmaxf(sqrtf(ssq), 1e-12f);
    }
    __syncthreads();

    // S = q . k  (4 independent accumulator chains)
    float att[64];
    const float* bmr = &bm[t * 68];
#pragma unroll
    for (int kk = 0; kk < 64; ++kk) {
        const ulonglong2* kr = (const ulonglong2*)&ks[kk * 36];
        u64 a0 = 0ull, a1 = 0ull, a2 = 0ull, a3 = 0ull;
#pragma unroll
        for (int j = 0; j < 4; ++j) {
            ulonglong2 p0 = kr[2 * j];
            ulonglong2 p1 = kr[2 * j + 1];
            a0 = ffma2(q2[4 * j + 0], p0.x, a0);
            a1 = ffma2(q2[4 * j + 1], p0.y, a1);
            a2 = ffma2(q2[4 * j + 2], p1.x, a2);
            a3 = ffma2(q2[4 * j + 3], p1.y, a3);
        }
        u64 sv = fadd2(fadd2(a0, a1), fadd2(a2, a3));
        float lo, hi; unpack2(sv, lo, hi);
        att[kk] = (lo + hi) * (rqs * rk[kk]) + bmr[kk];
    }

    // softmax over kk
    float m = att[0];
#pragma unroll
    for (int kk = 1; kk < 64; ++kk) m = fmaxf(m, att[kk]);
    float sum = 0.0f;
#pragma unroll
    for (int kk = 0; kk < 64; ++kk) { att[kk] = __expf(att[kk] - m); sum += att[kk]; }
    float rs = 1.0f / sum;

    // out = P @ V
    u64 o2[16];
#pragma unroll
    for (int p = 0; p < 16; ++p) o2[p] = 0ull;
#pragma unroll
    for (int kk = 0; kk < 64; ++kk) {
        u64 pp = pack2(att[kk], att[kk]);
        const ulonglong2* vr = (const ulonglong2*)&vs[kk * 36];
#pragma unroll
        for (int j = 0; j < 8; ++j) {
            ulonglong2 vv = vr[j];
            o2[2 * j]     = ffma2(pp, vv.x, o2[2 * j]);
            o2[2 * j + 1] = ffma2(pp, vv.y, o2[2 * j + 1]);
        }
    }

    // fused window reverse; emit hi/lo bf16 for proj GEMM
    int b = win >> 8;
    int y = ((wi >> 4) << 3) + (t >> 3);
    int x = ((wi & 15) << 3) + (t & 7);
    size_t tok = (size_t)(((b << 7) + y) * 128 + x);
    __nv_bfloat16* dh = &g_ah[tok * 128 + h * 32];
    __nv_bfloat16* dl = &g_al[tok * 128 + h * 32];
#pragma unroll
    for (int i = 0; i < 8; ++i) {
        float lo0, hi0, lo1, hi1;
        unpack2(o2[2 * i],     lo0, hi0);
        unpack2(o2[2 * i + 1], lo1, hi1);
        float4 v = make_float4(lo0 * rs, hi0 * rs, lo1 * rs, hi1 * rs);
        uint2 hh, ll; cvt_hilo4(v, hh, ll);
        *(uint2*)&dh[4 * i] = hh;
        *(uint2*)&dl[4 * i] = ll;
    }
}

// ---------------------------------------------------------------------------
// Kernel 3: proj GEMM (grid 2048 x 2) + bias -> d_out
// ---------------------------------------------------------------------------
__global__ void __launch_bounds__(256, 3) proj_mma_kernel(
    const float* __restrict__ pb, float* __restrict__ out)
{
    __shared__ __align__(16) char smem[SMEM_G];
    u32 sb = smem_u32(smem);
    int tid = threadIdx.x;
    int rm0 = blockIdx.x * 128;
    int n0  = blockIdx.y * 64;

    float acc[2][4][4];
#pragma unroll
    for (int mt = 0; mt < 2; ++mt)
#pragma unroll
        for (int nt = 0; nt < 4; ++nt)
#pragma unroll
            for (int e = 0; e < 4; ++e) acc[mt][nt][e] = 0.0f;

    int lane = tid & 31, wid = tid >> 5;
    int wm = wid & 3, wn = wid >> 2;

#pragma unroll
    for (int kc = 0; kc < 2; ++kc) {
        if (kc) __syncthreads();
        gemm_chunk_load(g_ah, g_al, g_wp_hi, g_wp_lo, smem, tid, rm0, n0, kc);
        __syncthreads();
        gemm_chunk_mma(sb, lane, wm, wn, acc);
    }

    int g = lane >> 2, t2 = (lane & 3) * 2;
    int colb = n0 + wn * 32 + t2;

    float bias0[4], bias1[4];
#pragma unroll
    for (int nt = 0; nt < 4; ++nt) {
        bias0[nt] = pb[colb + nt * 8];
        bias1[nt] = pb[colb + nt * 8 + 1];
    }

#pragma unroll
    for (int mt = 0; mt < 2; ++mt) {
#pragma unroll
        for (int half = 0; half < 2; ++half) {
            int gr = rm0 + wm * 32 + mt * 16 + g + half * 8;
            float* dst = &out[(size_t)gr * DIM];
#pragma unroll
            for (int nt = 0; nt < 4; ++nt) {
                float2 v = make_float2(acc[mt][nt][half * 2 + 0] + bias0[nt],
                                       acc[mt][nt][half * 2 + 1] + bias1[nt]);
                *(float2*)&dst[colb + nt * 8] = v;
            }
        }
    }
}

// ---------------------------------------------------------------------------
extern "C" void kernel_launch(void* const* d_in, const int* in_sizes, int n_in,
                              void* d_out, int out_size)
{
    const float* x           = (const float*)d_in[0];
    const float* mask        = (const float*)d_in[1];
    const float* qkv_w       = (const float*)d_in[2];
    const float* q_bias      = (const float*)d_in[3];
    const float* v_bias      = (const float*)d_in[4];
    const float* logit_scale = (const float*)d_in[5];
    const float* cpb_w1      = (const float*)d_in[6];
    const float* cpb_b1      = (const float*)d_in[7];
    const float* cpb_w2      = (const float*)d_in[8];
    const float* proj_w      = (const float*)d_in[9];
    const float* proj_b      = (const float*)d_in[10];
    float* out = (float*)d_out;

    prep_weights_kernel<<<64, 256>>>(qkv_w, proj_w);
    convert_x_kernel<<<2048, 256>>>(x);
    cpb_bias_kernel<<<1, 256>>>(cpb_w1, cpb_b1, cpb_w2);
    qkv_mma_kernel<<<dim3(2048, 6), 256>>>(q_bias, v_bias);
    attn_kernel<<<dim3(4096, 4), 64>>>(mask, logit_scale);
    proj_mma_kernel<<<dim3(2048, 2), 256>>>(proj_b, out);
}

// round 15
// speedup vs baseline: 1.0029x; 1.0029x over previous
#include <cuda_runtime.h>
#include <cuda_bf16.h>
#include <math.h>

// ---------------------------------------------------------------------------
// SwinV2 window attention, sm_103a (compute_103 PTX).
// GEMMs via mma.sync bf16 hi/lo (3-MMA), 48KB-smem tiles for occupancy.
// Pipeline: prep_weights + convert_x + cpb -> qkv_mma -> attn -> proj_mma
// ---------------------------------------------------------------------------

#define NTOK   262144           // 16*128*128 tokens
#define NWIN   4096
#define HEADS  4
#define DIM    128
#define QKVC   384
#define LOG100 4.605170185988091f

__device__ float g_qkv[(size_t)NWIN * 64 * QKVC];   // [win][n][384] q|k|v
__device__ float g_bias[HEADS * 64 * 64];
// activations pre-split to bf16 hi/lo
__device__ __nv_bfloat16 g_xh[(size_t)NTOK * 128], g_xl[(size_t)NTOK * 128];
__device__ __nv_bfloat16 g_ah[(size_t)NTOK * 128], g_al[(size_t)NTOK * 128];
// weights pre-transposed to [n][k], split into bf16 hi/lo
__device__ __nv_bfloat16 g_wq_hi[QKVC * 128], g_wq_lo[QKVC * 128];
__device__ __nv_bfloat16 g_wp_hi[DIM  * 128], g_wp_lo[DIM  * 128];

typedef unsigned long long u64;
typedef unsigned int u32;

__device__ __forceinline__ u64 pack2(float lo, float hi) {
    u64 r; asm("mov.b64 %0, {%1,%2};" : "=l"(r) : "f"(lo), "f"(hi)); return r;
}
__device__ __forceinline__ void unpack2(u64 v, float& lo, float& hi) {
    asm("mov.b64 {%0,%1}, %2;" : "=f"(lo), "=f"(hi) : "l"(v));
}
__device__ __forceinline__ u64 ffma2(u64 a, u64 b, u64 c) {
    u64 d; asm("fma.rn.f32x2 %0, %1, %2, %3;" : "=l"(d) : "l"(a), "l"(b), "l"(c));
    return d;
}
__device__ __forceinline__ u64 fadd2(u64 a, u64 b) {
    u64 d; asm("add.rn.f32x2 %0, %1, %2;" : "=l"(d) : "l"(a), "l"(b));
    return d;
}
__device__ __forceinline__ u32 smem_u32(const void* p) {
    u32 a; asm("{ .reg .u64 t; cvta.to.shared.u64 t, %1; cvt.u32.u64 %0, t; }"
               : "=r"(a) : "l"(p));
    return a;
}
__device__ __forceinline__ void ldsm4(u32* r, u32 addr) {
    asm volatile("ldmatrix.sync.aligned.m8n8.x4.shared.b16 {%0,%1,%2,%3}, [%4];"
                 : "=r"(r[0]), "=r"(r[1]), "=r"(r[2]), "=r"(r[3]) : "r"(addr));
}
__device__ __forceinline__ void mma16816(float* c, const u32* a, const u32* b) {
    asm volatile(
        "mma.sync.aligned.m16n8k16.row.col.f32.bf16.bf16.f32 "
        "{%0,%1,%2,%3}, {%4,%5,%6,%7}, {%8,%9}, {%0,%1,%2,%3};"
        : "+f"(c[0]), "+f"(c[1]), "+f"(c[2]), "+f"(c[3])
        : "r"(a[0]), "r"(a[1]), "r"(a[2]), "r"(a[3]), "r"(b[0]), "r"(b[1]));
}

__device__ __forceinline__ void cvt_hilo4(float4 v, uint2& h, uint2& l) {
    float f[4] = {v.x, v.y, v.z, v.w};
    u32 hs[4], ls[4];
#pragma unroll
    for (int j = 0; j < 4; ++j) {
        __nv_bfloat16 hb = __float2bfloat16(f[j]);
        float hf = __bfloat162float(hb);
        __nv_bfloat16 lb = __float2bfloat16(f[j] - hf);
        hs[j] = __bfloat16_as_ushort(hb);
        ls[j] = __bfloat16_as_ushort(lb);
    }
    h.x = hs[0] | (hs[1] << 16); h.y = hs[2] | (hs[3] << 16);
    l.x = ls[0] | (ls[1] << 16); l.y = ls[2] | (ls[3] << 16);
}

// ---------------------------------------------------------------------------
// GEMM tiles: 128M x 64N, K chunks of 64. smem 48KB (4 bf16 tiles).
// Tile rows are 64 bf16 = 128B; XOR swizzle on 16B chunks.
// ---------------------------------------------------------------------------
#define AH_OFF 0
#define AL_OFF 16384
#define BH_OFF 32768
#define BL_OFF 40960
#define SMEM_G 49152

__device__ __forceinline__ u32 swz64(int r, int c8) {
    return (u32)(r * 128 + ((c8 ^ (r & 7)) << 4));
}

__device__ __forceinline__ void gemm_chunk_load(
    const __nv_bfloat16* __restrict__ Ah, const __nv_bfloat16* __restrict__ Al,
    const __nv_bfloat16* __restrict__ Bh, const __nv_bfloat16* __restrict__ Bl,
    char* smem, int tid, int rm0, int n0, int kc)
{
#pragma unroll
    for (int l = 0; l < 4; ++l) {           // A: 128 rows x 64 k
        int i = tid + l * 256;
        int r = i >> 3, c8 = i & 7;
        u32 so = swz64(r, c8);
        size_t gs = (size_t)(rm0 + r) * 128 + kc * 64 + c8 * 8;
        *(uint4*)(smem + AH_OFF + so) = *(const uint4*)&Ah[gs];
        *(uint4*)(smem + AL_OFF + so) = *(const uint4*)&Al[gs];
    }
#pragma unroll
    for (int l = 0; l < 2; ++l) {           // B: 64 rows x 64 k
        int i = tid + l * 256;
        int r = i >> 3, c8 = i & 7;
        u32 so = swz64(r, c8);
        size_t gs = (size_t)(n0 + r) * 128 + kc * 64 + c8 * 8;
        *(uint4*)(smem + BH_OFF + so) = *(const uint4*)&Bh[gs];
        *(uint4*)(smem + BL_OFF + so) = *(const uint4*)&Bl[gs];
    }
}

// warp tile 32Mx32N: acc[2 mt][4 nt][4]
__device__ __forceinline__ void gemm_chunk_mma(u32 sb, int lane, int wm, int wn,
                                               float acc[2][4][4])
{
    int ar = (lane & 7) + ((lane >> 3) & 1) * 8;
    int ac = (lane >> 4) * 8;
    int br = (lane & 7) + (lane >> 4) * 8;
    int bc = ((lane >> 3) & 1) * 8;
#pragma unroll
    for (int k0 = 0; k0 < 64; k0 += 16) {
        u32 aH[2][4], aL[2][4];
#pragma unroll
        for (int mt = 0; mt < 2; ++mt) {
            int R = wm * 32 + mt * 16 + ar;
            u32 o = swz64(R, (k0 + ac) >> 3);
            ldsm4(aH[mt], sb + AH_OFF + o);
            ldsm4(aL[mt], sb + AL_OFF + o);
        }
        u32 bH[4][2], bL[4][2];
#pragma unroll
        for (int p = 0; p < 2; ++p) {
            int R = wn * 32 + p * 16 + br;
            u32 o = swz64(R, (k0 + bc) >> 3);
            u32 t4[4];
            ldsm4(t4, sb + BH_OFF + o);
            bH[p*2][0] = t4[0]; bH[p*2][1] = t4[1];
            bH[p*2+1][0] = t4[2]; bH[p*2+1][1] = t4[3];
            ldsm4(t4, sb + BL_OFF + o);
            bL[p*2][0] = t4[0]; bL[p*2][1] = t4[1];
            bL[p*2+1][0] = t4[2]; bL[p*2+1][1] = t4[3];
        }
#pragma unroll
        for (int mt = 0; mt < 2; ++mt)
#pragma unroll
            for (int nt = 0; nt < 4; ++nt) {
                mma16816(acc[mt][nt], aH[mt], bH[nt]);
                mma16816(acc[mt][nt], aH[mt], bL[nt]);
                mma16816(acc[mt][nt], aL[mt], bH[nt]);
            }
    }
}

// ---------------------------------------------------------------------------
// prep kernels
// ---------------------------------------------------------------------------
__global__ void prep_weights_kernel(const float* __restrict__ qkv_w,
                                    const float* __restrict__ proj_w)
{
    int tid = blockIdx.x * blockDim.x + threadIdx.x;
    for (int i = tid; i < QKVC * 128 + DIM * 128; i += gridDim.x * blockDim.x) {
        float w;
        __nv_bfloat16 *dh, *dl;
        int idx;
        if (i < QKVC * 128) {
            int n = i >> 7, k = i & 127;
            w = qkv_w[k * QKVC + n];
            dh = g_wq_hi; dl = g_wq_lo; idx = i;
        } else {
            int j = i - QKVC * 128;
            int n = j >> 7, k = j & 127;
            w = proj_w[k * DIM + n];
            dh = g_wp_hi; dl = g_wp_lo; idx = j;
        }
        __nv_bfloat16 hb = __float2bfloat16(w);
        __nv_bfloat16 lb = __float2bfloat16(w - __bfloat162float(hb));
        dh[idx] = hb; dl[idx] = lb;
    }
}

__global__ void convert_x_kernel(const float* __restrict__ X)
{
    int i = blockIdx.x * blockDim.x + threadIdx.x;
    const int total = NTOK * 128 / 4;
    for (; i < total; i += gridDim.x * blockDim.x) {
        float4 v = ((const float4*)X)[i];
        uint2 h, l; cvt_hilo4(v, h, l);
        *(uint2*)&g_xh[(size_t)i * 4] = h;
        *(uint2*)&g_xl[(size_t)i * 4] = l;
    }
}

__global__ void cpb_bias_kernel(const float* __restrict__ w1,
                                const float* __restrict__ b1,
                                const float* __restrict__ w2)
{
    __shared__ float tab[225 * 4];
    int t = threadIdx.x;
    if (t < 225) {
        int i = t / 15, j = t % 15;
        float v0 = (float)(i - 7) * (8.0f / 7.0f);
        float v1 = (float)(j - 7) * (8.0f / 7.0f);
        float t0 = copysignf(log2f(fabsf(v0) + 1.0f) * (1.0f / 3.0f), v0);
        float t1 = copysignf(log2f(fabsf(v1) + 1.0f) * (1.0f / 3.0f), v1);
        float a0 = 0.f, a1 = 0.f, a2 = 0.f, a3 = 0.f;
        for (int jj = 0; jj < 512; ++jj) {
            float hsum = fmaxf(t0 * w1[jj] + t1 * w1[512 + jj] + b1[jj], 0.0f);
            a0 += hsum * w2[jj * 4 + 0];
            a1 += hsum * w2[jj * 4 + 1];
            a2 += hsum * w2[jj * 4 + 2];
            a3 += hsum * w2[jj * 4 + 3];
        }
        tab[t * 4 + 0] = a0; tab[t * 4 + 1] = a1;
        tab[t * 4 + 2] = a2; tab[t * 4 + 3] = a3;
    }
    __syncthreads();
    for (int p = t; p < HEADS * 64 * 64; p += blockDim.x) {
        int h = p >> 12, q = (p >> 6) & 63, k = p & 63;
        int r0 = (q >> 3) - (k >> 3);
        int r1 = (q & 7) - (k & 7);
        int idx = (r0 + 7) * 15 + (r1 + 7);
        float bt = tab[idx * 4 + h];
        g_bias[p] = 16.0f / (1.0f + expf(-bt));
    }
}

// ---------------------------------------------------------------------------
// Kernel 1: QKV GEMM (grid 2048 x 6), fused bias + window-partition scatter
// ---------------------------------------------------------------------------
__global__ void __launch_bounds__(256, 3) qkv_mma_kernel(
    const float* __restrict__ qb, const float* __restrict__ vb)
{
    __shared__ __align__(16) char smem[SMEM_G];
    u32 sb = smem_u32(smem);
    int tid = threadIdx.x;
    int rm0 = blockIdx.x * 128;
    int n0  = blockIdx.y * 64;

    float acc[2][4][4];
#pragma unroll
    for (int mt = 0; mt < 2; ++mt)
#pragma unroll
        for (int nt = 0; nt < 4; ++nt)
#pragma unroll
            for (int e = 0; e < 4; ++e) acc[mt][nt][e] = 0.0f;

    int lane = tid & 31, wid = tid >> 5;
    int wm = wid & 3, wn = wid >> 2;

#pragma unroll
    for (int kc = 0; kc < 2; ++kc) {
        if (kc) __syncthreads();
        gemm_chunk_load(g_xh, g_xl, g_wq_hi, g_wq_lo, smem, tid, rm0, n0, kc);
        __syncthreads();
        gemm_chunk_mma(sb, lane, wm, wn, acc);
    }

    int g = lane >> 2, t2 = (lane & 3) * 2;
    int colb = n0 + wn * 32 + t2;

    float bias0[4], bias1[4];
#pragma unroll
    for (int nt = 0; nt < 4; ++nt) {
        int c = colb + nt * 8;
        bias0[nt] = (c < 128) ? qb[c] : ((c < 256) ? 0.0f : vb[c - 256]);
        c += 1;
        bias1[nt] = (c < 128) ? qb[c] : ((c < 256) ? 0.0f : vb[c - 256]);
    }

#pragma unroll
    for (int mt = 0; mt < 2; ++mt) {
#pragma unroll
        for (int half = 0; half < 2; ++half) {
            int gr = rm0 + wm * 32 + mt * 16 + g + half * 8;
            int b   = gr >> 14;
            int rem = gr & 16383;
            int y = rem >> 7, xx = rem & 127;
            int wi = ((y >> 3) << 4) + (xx >> 3);
            int n  = ((y & 7) << 3) + (xx & 7);
            float* dst = &g_qkv[(size_t)(((b << 8) + wi) * 64 + n) * QKVC];
#pragma unroll
            for (int nt = 0; nt < 4; ++nt) {
                float2 v = make_float2(acc[mt][nt][half * 2 + 0] + bias0[nt],
                                       acc[mt][nt][half * 2 + 1] + bias1[nt]);
                *(float2*)&dst[colb + nt * 8] = v;
            }
        }
    }
}

// ---------------------------------------------------------------------------
// Kernel 2: per-(window, head) cosine attention, v3 (float4 smem, 4-way ILP)
// ---------------------------------------------------------------------------
__global__ void __launch_bounds__(64) attn_kernel(
    const float* __restrict__ mask, const float* __restrict__ logit_scale)
{
    __shared__ __align__(16) float ks[64 * 36];
    __shared__ __align__(16) float vs[64 * 36];
    __shared__ float rk[64];
    __shared__ __align__(16) float bm[64 * 68];

    int t = threadIdx.x;
    int win = blockIdx.x;
    int h   = blockIdx.y;
    int wi  = win & 255;

    const float* base = &g_qkv[(size_t)win * 64 * QKVC];

    // K,V tiles (padded stride 36 floats), float4-coalesced
#pragma unroll
    for (int i = 0; i < 8; ++i) {
        int idx4 = t + i * 64;
        int n = idx4 >> 3, d4 = (idx4 & 7) << 2;
        *(float4*)&vs[n * 36 + d4] = *(const float4*)&base[n * QKVC + 256 + h * 32 + d4];
        *(float4*)&ks[n * 36 + d4] = *(const float4*)&base[n * QKVC + 128 + h * 32 + d4];
    }
    // bias + mask (padded stride 68)
    {
        const float* gb = &g_bias[h * 4096];
        const float* gm = &mask[(size_t)wi * 4096];
#pragma unroll
        for (int i = 0; i < 16; ++i) {
            int idx4 = t + i * 64;
            int q = idx4 >> 4, k4 = (idx4 & 15) << 2;
            float4 a = *(const float4*)&gb[q * 64 + k4];
            float4 b = *(const float4*)&gm[q * 64 + k4];
            *(float4*)&bm[q * 68 + k4] =
                make_float4(a.x + b.x, a.y + b.y, a.z + b.z, a.w + b.w);
        }
    }
    // own query row into regs
    float4 q4[8];
    const float* qp = &base[t * QKVC + h * 32];
    float ssqq = 0.0f;
#pragma unroll
    for (int i = 0; i < 8; ++i) {
        q4[i] = *(const float4*)(qp + 4 * i);
        ssqq += q4[i].x * q4[i].x + q4[i].y * q4[i].y
              + q4[i].z * q4[i].z + q4[i].w * q4[i].w;
    }
    float rq = 1.0f / fmaxf(sqrtf(ssqq), 1e-12f);
    float s  = expf(fminf(logit_scale[h], LOG100));
    float rqs = rq * s;
    u64 q2[16];
#pragma unroll
    for (int i = 0; i < 8; ++i) {
        q2[2 * i]     = pack2(q4[i].x, q4[i].y);
        q2[2 * i + 1] = pack2(q4[i].z, q4[i].w);
    }
    __syncthreads();

    // per-row K inverse norms (thread t handles row t)
    {
        float ssq = 0.0f;
#pragma unroll
        for (int j = 0; j < 8; ++j) {
            float4 kv = *(const float4*)&ks[t * 36 + j * 4];
            ssq += kv.x * kv.x + kv.y * kv.y + kv.z * kv.z + kv.w * kv.w;
        }
        rk[t] = 1.0f / fmaxf(sqrtf(ssq), 1e-12f);
    }
    __syncthreads();

    // S = q . k  (4 independent accumulator chains)
    float att[64];
    const float* bmr = &bm[t * 68];
#pragma unroll
    for (int kk = 0; kk < 64; ++kk) {
        const ulonglong2* kr = (const ulonglong2*)&ks[kk * 36];
        u64 a0 = 0ull, a1 = 0ull, a2 = 0ull, a3 = 0ull;
#pragma unroll
        for (int j = 0; j < 4; ++j) {
            ulonglong2 p0 = kr[2 * j];
            ulonglong2 p1 = kr[2 * j + 1];
            a0 = ffma2(q2[4 * j + 0], p0.x, a0);
            a1 = ffma2(q2[4 * j + 1], p0.y, a1);
            a2 = ffma2(q2[4 * j + 2], p1.x, a2);
            a3 = ffma2(q2[4 * j + 3], p1.y, a3);
        }
        u64 sv = fadd2(fadd2(a0, a1), fadd2(a2, a3));
        float lo, hi; unpack2(sv, lo, hi);
        att[kk] = (lo + hi) * (rqs * rk[kk]) + bmr[kk];
    }

    // softmax over kk
    float m = att[0];
#pragma unroll
    for (int kk = 1; kk < 64; ++kk) m = fmaxf(m, att[kk]);
    float sum = 0.0f;
#pragma unroll
    for (int kk = 0; kk < 64; ++kk) { att[kk] = __expf(att[kk] - m); sum += att[kk]; }
    float rs = 1.0f / sum;

    // out = P @ V
    u64 o2[16];
#pragma unroll
    for (int p = 0; p < 16; ++p) o2[p] = 0ull;
#pragma unroll
    for (int kk = 0; kk < 64; ++kk) {
        u64 pp = pack2(att[kk], att[kk]);
        const ulonglong2* vr = (const ulonglong2*)&vs[kk * 36];
#pragma unroll
        for (int j = 0; j < 8; ++j) {
            ulonglong2 vv = vr[j];
            o2[2 * j]     = ffma2(pp, vv.x, o2[2 * j]);
            o2[2 * j + 1] = ffma2(pp, vv.y, o2[2 * j + 1]);
        }
    }

    // fused window reverse; emit hi/lo bf16 for proj GEMM
    int b = win >> 8;
    int y = ((wi >> 4) << 3) + (t >> 3);
    int x = ((wi & 15) << 3) + (t & 7);
    size_t tok = (size_t)(((b << 7) + y) * 128 + x);
    __nv_bfloat16* dh = &g_ah[tok * 128 + h * 32];
    __nv_bfloat16* dl = &g_al[tok * 128 + h * 32];
#pragma unroll
    for (int i = 0; i < 8; ++i) {
        float lo0, hi0, lo1, hi1;
        unpack2(o2[2 * i],     lo0, hi0);
        unpack2(o2[2 * i + 1], lo1, hi1);
        float4 v = make_float4(lo0 * rs, hi0 * rs, lo1 * rs, hi1 * rs);
        uint2 hh, ll; cvt_hilo4(v, hh, ll);
        *(uint2*)&dh[4 * i] = hh;
        *(uint2*)&dl[4 * i] = ll;
    }
}

// ---------------------------------------------------------------------------
// Kernel 3: proj GEMM (grid 2048 x 2) + bias -> d_out
// ---------------------------------------------------------------------------
__global__ void __launch_bounds__(256, 3) proj_mma_kernel(
    const float* __restrict__ pb, float* __restrict__ out)
{
    __shared__ __align__(16) char smem[SMEM_G];
    u32 sb = smem_u32(smem);
    int tid = threadIdx.x;
    int rm0 = blockIdx.x * 128;
    int n0  = blockIdx.y * 64;

    float acc[2][4][4];
#pragma unroll
    for (int mt = 0; mt < 2; ++mt)
#pragma unroll
        for (int nt = 0; nt < 4; ++nt)
#pragma unroll
            for (int e = 0; e < 4; ++e) acc[mt][nt][e] = 0.0f;

    int lane = tid & 31, wid = tid >> 5;
    int wm = wid & 3, wn = wid >> 2;

#pragma unroll
    for (int kc = 0; kc < 2; ++kc) {
        if (kc) __syncthreads();
        gemm_chunk_load(g_ah, g_al, g_wp_hi, g_wp_lo, smem, tid, rm0, n0, kc);
        __syncthreads();
        gemm_chunk_mma(sb, lane, wm, wn, acc);
    }

    int g = lane >> 2, t2 = (lane & 3) * 2;
    int colb = n0 + wn * 32 + t2;

    float bias0[4], bias1[4];
#pragma unroll
    for (int nt = 0; nt < 4; ++nt) {
        bias0[nt] = pb[colb + nt * 8];
        bias1[nt] = pb[colb + nt * 8 + 1];
    }

#pragma unroll
    for (int mt = 0; mt < 2; ++mt) {
#pragma unroll
        for (int half = 0; half < 2; ++half) {
            int gr = rm0 + wm * 32 + mt * 16 + g + half * 8;
            float* dst = &out[(size_t)gr * DIM];
#pragma unroll
            for (int nt = 0; nt < 4; ++nt) {
                float2 v = make_float2(acc[mt][nt][half * 2 + 0] + bias0[nt],
                                       acc[mt][nt][half * 2 + 1] + bias1[nt]);
                *(float2*)&dst[colb + nt * 8] = v;
            }
        }
    }
}

// ---------------------------------------------------------------------------
extern "C" void kernel_launch(void* const* d_in, const int* in_sizes, int n_in,
                              void* d_out, int out_size)
{
    const float* x           = (const float*)d_in[0];
    const float* mask        = (const float*)d_in[1];
    const float* qkv_w       = (const float*)d_in[2];
    const float* q_bias      = (const float*)d_in[3];
    const float* v_bias      = (const float*)d_in[4];
    const float* logit_scale = (const float*)d_in[5];
    const float* cpb_w1      = (const float*)d_in[6];
    const float* cpb_b1      = (const float*)d_in[7];
    const float* cpb_w2      = (const float*)d_in[8];
    const float* proj_w      = (const float*)d_in[9];
    const float* proj_b      = (const float*)d_in[10];
    float* out = (float*)d_out;

    prep_weights_kernel<<<64, 256>>>(qkv_w, proj_w);
    convert_x_kernel<<<2048, 256>>>(x);
    cpb_bias_kernel<<<1, 256>>>(cpb_w1, cpb_b1, cpb_w2);
    qkv_mma_kernel<<<dim3(2048, 6), 256>>>(q_bias, v_bias);
    attn_kernel<<<dim3(4096, 4), 64>>>(mask, logit_scale);
    proj_mma_kernel<<<dim3(2048, 2), 256>>>(proj_b, out);
}